// round 2
// baseline (speedup 1.0000x reference)
#include <cuda_runtime.h>
#include <cstdint>

#define T_LEN   1048576
#define KSTEPS  512
#define NSLOTS  4
#define NCHUNK  (T_LEN / KSTEPS)

// shared memory layout (bytes)
#define OFF_PF   0                         // p_full[4]   (8B each)
#define OFF_PC   32                        // p_cons[4]
#define OFF_WF   64                        // w_full[4]
#define OFF_WE   96                        // w_free[4]
#define OFF_P    256                       // p ring: 4 slots x 512 steps x 64B
#define PSLOT    (KSTEPS * 64)
#define OFF_W    (OFF_P + NSLOTS * PSLOT)  // w ring: 4 slots x 512 steps x 32B
#define WSLOT    (KSTEPS * 32)
#define SMEM_SZ  (OFF_W + NSLOTS * WSLOT)  // 196864 bytes

typedef unsigned long long ull;
typedef unsigned int u32;

__device__ __forceinline__ void mbar_init(u32 a, u32 cnt) {
    asm volatile("mbarrier.init.shared.b64 [%0], %1;" :: "r"(a), "r"(cnt) : "memory");
}
__device__ __forceinline__ void mbar_arrive(u32 a) {
    asm volatile("mbarrier.arrive.shared.b64 _, [%0];" :: "r"(a) : "memory");
}
__device__ __forceinline__ void mbar_wait(u32 a, u32 par) {
    u32 done;
    asm volatile(
        "{\n\t.reg .pred p;\n\t"
        "mbarrier.try_wait.parity.acquire.cta.shared::cta.b64 p, [%1], %2;\n\t"
        "selp.b32 %0, 1, 0, p;\n\t}"
        : "=r"(done) : "r"(a), "r"(par) : "memory");
    if (!done) {
        asm volatile(
            "{\n\t.reg .pred P1;\n\t"
            "WL_%=:\n\t"
            "mbarrier.try_wait.parity.acquire.cta.shared::cta.b64 P1, [%0], %1, 0x989680;\n\t"
            "@P1 bra.uni WD_%=;\n\t"
            "bra.uni WL_%=;\n\t"
            "WD_%=:\n\t}"
            :: "r"(a), "r"(par) : "memory");
    }
}

// packed f32x2 add: bit-exact two IEEE rn f32 adds in one instruction
__device__ __forceinline__ ull addx2(ull a, ull b) {
    ull r; asm("add.rn.f32x2 %0, %1, %2;" : "=l"(r) : "l"(a), "l"(b)); return r;
}
__device__ __forceinline__ float f2lo(ull v) {
    float f; asm("{ .reg .b32 h; mov.b64 {%0, h}, %1; }" : "=f"(f) : "l"(v)); return f;
}
__device__ __forceinline__ float f2hi(ull v) {
    float f; asm("{ .reg .b32 l; mov.b64 {l, %0}, %1; }" : "=f"(f) : "l"(v)); return f;
}
__device__ __forceinline__ ull fpack(float x, float y) {
    ull r; asm("mov.b64 %0, {%1, %2};" : "=l"(r) : "f"(x), "f"(y)); return r;
}
__device__ __forceinline__ void lds2(u32 a, ull& x, ull& y) {
    asm volatile("ld.shared.v2.u64 {%0, %1}, [%2];" : "=l"(x), "=l"(y) : "r"(a));
}
__device__ __forceinline__ void sts4(u32 a, float x, float y, float z, float w) {
    asm volatile("st.shared.v4.f32 [%0], {%1, %2, %3, %4};"
                 :: "r"(a), "f"(x), "f"(y), "f"(z), "f"(w) : "memory");
}

__global__ void __launch_bounds__(352, 1)
va_main(const float* __restrict__ y, const float* __restrict__ sp, float* __restrict__ out)
{
    extern __shared__ char smem[];
    u32 sb = (u32)__cvta_generic_to_shared(smem);
    int tid = threadIdx.x, wid = tid >> 5, lane = tid & 31;

    if (tid == 0) {
        for (int s = 0; s < NSLOTS; s++) {
            mbar_init(sb + OFF_PF + 8 * s, 64); // 64 fetch lanes arrive
            mbar_init(sb + OFF_PC + 8 * s, 1);  // producer arrives
            mbar_init(sb + OFF_WF + 8 * s, 1);  // producer arrives
            mbar_init(sb + OFF_WE + 8 * s, 8);  // 8 bit-warp leaders arrive
        }
    }
    __syncthreads();

    if (wid == 0) {
        // ---------------- serial Viterbi producer (single lane) ----------------
        if (lane == 0) {
            // packed state pairs {w0,w1},{w2,w3},{w4,w5},{w6,w7}; v0 = zeros
            ull w01 = 0ull, w23 = 0ull, w45 = 0ull, w67 = 0ull;
            for (int c = 0; c < NCHUNK; c++) {
                int s = c & 3;
                mbar_wait(sb + OFF_PF + 8 * s, (c >> 2) & 1);
                if (c >= NSLOTS) mbar_wait(sb + OFF_WE + 8 * s, ((c - NSLOTS) >> 2) & 1);
                u32 pb = sb + OFF_P + s * PSLOT;
                u32 wb = sb + OFF_W + s * WSLOT;
                #pragma unroll 8
                for (int k = 0; k < KSTEPS; k++) {
                    ull p0, p1, p2, p3, p4, p5, p6, p7;
                    u32 pa = pb + k * 64;
                    lds2(pa,      p0, p1);
                    lds2(pa + 16, p2, p3);
                    lds2(pa + 32, p4, p5);
                    lds2(pa + 48, p6, p7);
                    // m[u] = w[u&7] + p[u], packed two-at-a-time
                    ull m0 = addx2(w01, p0), m1 = addx2(w23, p1);
                    ull m2 = addx2(w45, p2), m3 = addx2(w67, p3);
                    ull m4 = addx2(w01, p4), m5 = addx2(w23, p5);
                    ull m6 = addx2(w45, p6), m7 = addx2(w67, p7);
                    // out[q] = min(m[2q], m[2q+1])  (horizontal within pair)
                    float o0 = fminf(f2lo(m0), f2hi(m0));
                    float o1 = fminf(f2lo(m1), f2hi(m1));
                    float o2 = fminf(f2lo(m2), f2hi(m2));
                    float o3 = fminf(f2lo(m3), f2hi(m3));
                    float o4 = fminf(f2lo(m4), f2hi(m4));
                    float o5 = fminf(f2lo(m5), f2hi(m5));
                    float o6 = fminf(f2lo(m6), f2hi(m6));
                    float o7 = fminf(f2lo(m7), f2hi(m7));
                    u32 wa = wb + k * 32;
                    sts4(wa,      o0, o1, o2, o3);
                    sts4(wa + 16, o4, o5, o6, o7);
                    w01 = fpack(o0, o1); w23 = fpack(o2, o3);
                    w45 = fpack(o4, o5); w67 = fpack(o6, o7);
                }
                mbar_arrive(sb + OFF_PC + 8 * s);
                mbar_arrive(sb + OFF_WF + 8 * s);
            }
        }
    } else if (wid <= 2) {
        // ---------------- branch-metric producers: p[t][u] = |y[t] - sp[u]| ----
        int base = (wid - 1) * 32 + lane;   // 0..63
        int quad = base & 3;                // fixed 4-state group per lane
        float s0 = sp[quad * 4 + 0], s1 = sp[quad * 4 + 1];
        float s2 = sp[quad * 4 + 2], s3 = sp[quad * 4 + 3];
        for (int c = 0; c < NCHUNK; c++) {
            int s = c & 3;
            if (c >= NSLOTS) mbar_wait(sb + OFF_PC + 8 * s, ((c - NSLOTS) >> 2) & 1);
            u32 pb = sb + OFF_P + s * PSLOT;
            const float* yc = y + c * KSTEPS;
            #pragma unroll 4
            for (int it = 0; it < 32; it++) {
                int idx = it * 64 + base;
                int k = idx >> 2;           // step within chunk
                float yv = __ldg(&yc[k]);
                sts4(pb + k * 64 + quad * 16,
                     fabsf(yv - s0), fabsf(yv - s1), fabsf(yv - s2), fabsf(yv - s3));
            }
            mbar_arrive(sb + OFF_PF + 8 * s);
        }
    } else {
        // ---------------- bit extractors: bit[t] = argmin(w_t) % 2 -------------
        int btid = tid - 96;                // 0..255
        if (btid == 0) out[0] = 0.0f;       // v_0 = zeros -> argmin = 0 -> bit 0
        const float4* wr = (const float4*)(smem + OFF_W);
        for (int c = 0; c < NCHUNK; c++) {
            int s = c & 3;
            mbar_wait(sb + OFF_WF + 8 * s, (c >> 2) & 1);
            #pragma unroll
            for (int r = 0; r < 2; r++) {
                int k = r * 256 + btid;
                int i = c * KSTEPS + k;     // producer step index; W[i] = w_{i+1}
                if (i != T_LEN - 1) {
                    const float4* p = wr + (size_t)(s * KSTEPS + k) * 2;
                    float4 a = p[0], b = p[1];
                    // first-index argmin over 8 (strict < keeps lowest index,
                    // matching jnp.argmin tie-breaking; w[s]==w[s+8] so 8 suffice)
                    float best = a.x; int bi = 0;
                    if (a.y < best) { best = a.y; bi = 1; }
                    if (a.z < best) { best = a.z; bi = 2; }
                    if (a.w < best) { best = a.w; bi = 3; }
                    if (b.x < best) { best = b.x; bi = 4; }
                    if (b.y < best) { best = b.y; bi = 5; }
                    if (b.z < best) { best = b.z; bi = 6; }
                    if (b.w < best) {            bi = 7; }
                    out[i + 1] = (float)(bi & 1);
                }
            }
            __syncwarp();
            if (lane == 0) mbar_arrive(sb + OFF_WE + 8 * s);
        }
    }
}

extern "C" void kernel_launch(void* const* d_in, const int* in_sizes, int n_in,
                              void* d_out, int out_size)
{
    const float* a = (const float*)d_in[0];
    const float* b = (const float*)d_in[1];
    const float* y;
    const float* sp;
    if (in_sizes[0] == 16) { sp = a; y = b; }
    else                   { y = a;  sp = b; }

    cudaFuncSetAttribute(va_main, cudaFuncAttributeMaxDynamicSharedMemorySize, SMEM_SZ);
    va_main<<<1, 352, SMEM_SZ>>>(y, sp, (float*)d_out);
}